// round 16
// baseline (speedup 1.0000x reference)
#include <cuda_runtime.h>

#define PI_F 3.14159265358979323846f
#define RS2 0.70710678118654752440f
#define FULL 0xffffffffu

// One warp (= one CTA) simulates the exact 7-qubit lightcone of z_q for one
// (row, qubit). Lane bits = (b0,b1,b2,b4,b6); register index j = b3 + 2*b5.
// Geometry: grid = 1024 CTAs of 32 threads (max SM spread) — best measured.
// Prep split across half-warps:
//   lanes 0..15  -> x-dependent chain: LDG(x) -> tanh -> ONE sincos
//   lanes 16..31 -> x-independent tables (h1, cis h2, end RY, cis(wry0/2)).
// Merged mid-RY cis((wry0+e)/2) built by angle addition (shfl from high lanes).
// Final reduce: fixed-point redux.sync.add.s32 (one warp-collective op instead
// of a 5-stage shfl ladder). Safe: sum(|acc_i|) <= total probability = 1, so
// scale 2^30 cannot overflow int32; rounding error <= ~1.5e-8.
__global__ __launch_bounds__(32) void qmain(
        const float* __restrict__ x, const float* __restrict__ wcrz,
        const float* __restrict__ wry, const float* __restrict__ scal,
        float* __restrict__ out) {
    __shared__ float2 Wu[16];   // (u0,u1): init amps RY(enc)·H|0>
    __shared__ float2 Wm[16];   // (cos,sin) merged mid RY (w0+enc)/2
    __shared__ float  Wh1[16];  // layer-0 CRZ half-angle
    __shared__ float2 Wh2[16];  // cis(layer-1 CRZ half-angle)
    __shared__ float2 We[16];   // (cos,sin) end RY w1/2

    int c = blockIdx.x;
    int r = c >> 4, q = c & 15;            // row 0..63, qubit 0..15
    int lane = threadIdx.x;
    int bb = r >> 3, p = r & 7;

    int qq = lane & 15;
    float wx = 0.f, wy = 0.f;              // high lanes: cis(wry0/2)
    float sh = 0.f, ch = 0.f;              // low lanes: cis(e/2)
    if (lane >= 16) {
        // x-independent work, overlaps the low half-warp's LDG->tanh chain
        Wh1[qq] = 0.5f * wcrz[qq];
        float s2, c2; __sincosf(0.5f * wcrz[16 + qq], &s2, &c2);
        Wh2[qq] = make_float2(c2, s2);
        float se_, ce_; __sincosf(0.5f * wry[16 + qq], &se_, &ce_);
        We[qq] = make_float2(ce_, se_);
        __sincosf(0.5f * wry[qq], &wy, &wx);   // cis(wry0/2) for the low lanes
    } else {
        float xv = x[bb * 128 + (qq >> 2) * 32 + p * 4 + (qq & 3)] * scal[0];
        float ex = __expf(2.f * xv);
        float e = __fdividef(ex - 1.f, ex + 1.f) * PI_F;   // pi * tanh(xv)
        __sincosf(0.5f * e, &sh, &ch);                     // the ONLY chained sincos
    }
    float cwm = __shfl_sync(FULL, wx, 16 + qq);
    float swm = __shfl_sync(FULL, wy, 16 + qq);
    if (lane < 16) {
        Wu[qq] = make_float2((ch - sh) * RS2, (ch + sh) * RS2);
        // cis((wry0+e)/2) = cis(wry0/2) * cis(e/2)
        Wm[qq] = make_float2(cwm * ch - swm * sh, swm * ch + cwm * sh);
    }
    __syncwarp();

    // window qubits: local bit k <-> global qubit q-3+k (mod 16)
    int p0 = (q + 13) & 15, p1 = (q + 14) & 15, p2 = (q + 15) & 15;
    int p4 = (q + 1) & 15,  p5 = (q + 2) & 15,  p6 = (q + 3) & 15;
    int b0 = lane & 1, b1 = (lane >> 1) & 1, b2 = (lane >> 2) & 1;
    int b4 = (lane >> 3) & 1, b6 = (lane >> 4) & 1;

    // warp-broadcast smem reads
    float2 U0 = Wu[p0], U1 = Wu[p1], U2 = Wu[p2];
    float2 Uq = Wu[q],  U4 = Wu[p4], U5 = Wu[p5], U6 = Wu[p6];
    float h1p0 = Wh1[p0], h1p1 = Wh1[p1], h1p2 = Wh1[p2];
    float h1q = Wh1[q], h1p4 = Wh1[p4], h1p5 = Wh1[p5];
    float2 M1 = Wm[p1], Mq = Wm[q], M5 = Wm[p5];
    float2 Ha = Wh2[p1], Hb = Wh2[q];
    float2 E = We[q];

    // init product amplitude over lane bits
    float base = (b0 ? U0.y : U0.x) * (b1 ? U1.y : U1.x) * (b2 ? U2.y : U2.x)
               * (b4 ? U4.y : U4.x) * (b6 ? U6.y : U6.x);
    // D1 ring phase: control? (target? +h : -h) : 0 over the 6 window pairs
    float phiL = (b0 ? (b1 ? h1p0 : -h1p0) : 0.f)
               + (b1 ? (b2 ? h1p1 : -h1p1) : 0.f);
    float A0 = b2 ? -h1p2 : 0.f;                               // b3 = 0
    float A1 = (b2 ? h1p2 : 0.f) + (b4 ? h1q : -h1q);          // b3 = 1
    float B0 = b4 ? -h1p4 : 0.f;                               // b5 = 0
    float B1 = (b4 ? h1p4 : 0.f) + (b6 ? h1p5 : -h1p5);        // b5 = 1

    float vr[4], vi[4];
    {
        float ang[4] = { phiL + A0 + B0, phiL + A1 + B0,
                         phiL + A0 + B1, phiL + A1 + B1 };     // j = b3 + 2*b5
        float fj[4] = { base * Uq.x * U5.x, base * Uq.y * U5.x,
                        base * Uq.x * U5.y, base * Uq.y * U5.y };
#pragma unroll
        for (int j = 0; j < 4; j++) {
            float s_, c_; __sincosf(ang[j], &s_, &c_);
            vr[j] = fj[j] * c_; vi[j] = fj[j] * s_;
        }
    }
    // mid RY on qubit q-2 (lane bit 1): the only shfl gate
    {
        float cc = M1.x, sg = b1 ? M1.y : -M1.y;
#pragma unroll
        for (int j = 0; j < 4; j++) {
            float pr = __shfl_xor_sync(FULL, vr[j], 2);
            float pi = __shfl_xor_sync(FULL, vi[j], 2);
            vr[j] = cc * vr[j] + sg * pr;
            vi[j] = cc * vi[j] + sg * pi;
        }
    }
    // mid RY on qubit q (register bit b3): pairs (0,1),(2,3)
    {
        float cc = Mq.x, ss = Mq.y;
#pragma unroll
        for (int jj = 0; jj < 4; jj += 2) {
            float r0 = vr[jj], r1 = vr[jj + 1];
            vr[jj] = cc * r0 - ss * r1;  vr[jj + 1] = ss * r0 + cc * r1;
            float i0 = vi[jj], i1 = vi[jj + 1];
            vi[jj] = cc * i0 - ss * i1;  vi[jj + 1] = ss * i0 + cc * i1;
        }
    }
    // mid RY on qubit q+2 (register bit b5): pairs (0,2),(1,3)
    {
        float cc = M5.x, ss = M5.y;
#pragma unroll
        for (int jj = 0; jj < 2; jj++) {
            float r0 = vr[jj], r1 = vr[jj + 2];
            vr[jj] = cc * r0 - ss * r1;  vr[jj + 2] = ss * r0 + cc * r1;
            float i0 = vi[jj], i1 = vi[jj + 2];
            vi[jj] = cc * i0 - ss * i1;  vi[jj + 2] = ss * i0 + cc * i1;
        }
    }
    // D2 diagonal: CRZ(q-2 -> q) uses (b1,b3); CRZ(q -> q+2) uses (b3,b5)
    {
        float pr0 = b1 ? Ha.x : 1.f, pi0 = b1 ? -Ha.y : 0.f;   // b3 = 0 factor
        float prA = pr0,            piA = b1 ?  Ha.y : 0.f;    // b3 = 1 base
#pragma unroll
        for (int jj = 0; jj < 4; jj += 2) {                    // j = 0, 2 (b3 = 0)
            float nr = vr[jj] * pr0 - vi[jj] * pi0;
            vi[jj] = vr[jj] * pi0 + vi[jj] * pr0;
            vr[jj] = nr;
        }
        float pr1 = prA * Hb.x + piA * Hb.y, pi1 = -prA * Hb.y + piA * Hb.x;
        float pr3 = prA * Hb.x - piA * Hb.y, pi3 =  prA * Hb.y + piA * Hb.x;
        float nr1 = vr[1] * pr1 - vi[1] * pi1;
        vi[1] = vr[1] * pi1 + vi[1] * pr1; vr[1] = nr1;
        float nr3 = vr[3] * pr3 - vi[3] * pi3;
        vi[3] = vr[3] * pi3 + vi[3] * pr3; vr[3] = nr3;
    }
    // end RY on qubit q (register bit b3)
    {
        float cc = E.x, ss = E.y;
#pragma unroll
        for (int jj = 0; jj < 4; jj += 2) {
            float r0 = vr[jj], r1 = vr[jj + 1];
            vr[jj] = cc * r0 - ss * r1;  vr[jj + 1] = ss * r0 + cc * r1;
            float i0 = vi[jj], i1 = vi[jj + 1];
            vi[jj] = cc * i0 - ss * i1;  vi[jj + 1] = ss * i0 + cc * i1;
        }
    }
    // z_q = sum (1 - 2*b3) |amp|^2 ; b3 = j&1
    float acc = (vr[0] * vr[0] + vi[0] * vi[0]) - (vr[1] * vr[1] + vi[1] * vi[1])
              + (vr[2] * vr[2] + vi[2] * vi[2]) - (vr[3] * vr[3] + vi[3] * vi[3]);
    // fixed-point warp reduction: one redux.sync.add.s32 (sm_80+) replaces the
    // 5-stage shuffle ladder. |sum of |acc|| <= 1 -> 2^30 scale cannot overflow.
    int ia = __float2int_rn(acc * 1073741824.0f);
    int red;
    asm volatile("redux.sync.add.s32 %0, %1, 0xffffffff;" : "=r"(red) : "r"(ia));
    if (lane == 0) {
        float z = (float)red * 9.313225746154785e-10f;   // 2^-30
        out[bb * 128 + (q >> 2) * 32 + p * 4 + (q & 3)] = fminf(1.f, fmaxf(-1.f, z));
    }
}

extern "C" void kernel_launch(void* const* d_in, const int* in_sizes, int n_in,
                              void* d_out, int out_size) {
    const float* x    = (const float*)d_in[0];
    const float* wcrz = (const float*)d_in[1];
    const float* wry  = (const float*)d_in[2];
    const float* sc   = (const float*)d_in[3];
    (void)in_sizes; (void)n_in; (void)out_size;
    qmain<<<1024, 32>>>(x, wcrz, wry, sc, (float*)d_out);
}

// round 17
// speedup vs baseline: 1.0147x; 1.0147x over previous
#include <cuda_runtime.h>

#define PI_F 3.14159265358979323846f
#define RS2 0.70710678118654752440f
#define FULL 0xffffffffu

// FINAL (best-measured, R14): one warp (= one CTA) simulates the exact
// 7-qubit lightcone of z_q for one (row, qubit).
// Lane bits = (b0,b1,b2,b4,b6); register index j = b3 + 2*b5.
// Geometry: grid = 1024 CTAs of 32 threads (max SM spread).
// Prep split across half-warps:
//   lanes 0..15  -> x-dependent chain: LDG(x) -> tanh -> ONE sincos
//   lanes 16..31 -> x-independent tables (h1, cis h2, end RY, cis(wry0/2)).
// Merged mid-RY cis((wry0+e)/2) built by angle addition (shfl from high lanes).
// Tables in per-CTA smem; reads are warp-broadcast LDS; __syncwarp only.
__global__ __launch_bounds__(32) void qmain(
        const float* __restrict__ x, const float* __restrict__ wcrz,
        const float* __restrict__ wry, const float* __restrict__ scal,
        float* __restrict__ out) {
    __shared__ float2 Wu[16];   // (u0,u1): init amps RY(enc)·H|0>
    __shared__ float2 Wm[16];   // (cos,sin) merged mid RY (w0+enc)/2
    __shared__ float  Wh1[16];  // layer-0 CRZ half-angle
    __shared__ float2 Wh2[16];  // cis(layer-1 CRZ half-angle)
    __shared__ float2 We[16];   // (cos,sin) end RY w1/2

    int c = blockIdx.x;
    int r = c >> 4, q = c & 15;            // row 0..63, qubit 0..15
    int lane = threadIdx.x;
    int bb = r >> 3, p = r & 7;

    int qq = lane & 15;
    float wx = 0.f, wy = 0.f;              // high lanes: cis(wry0/2)
    float sh = 0.f, ch = 0.f;              // low lanes: cis(e/2)
    if (lane >= 16) {
        // x-independent work, overlaps the low half-warp's LDG->tanh chain
        Wh1[qq] = 0.5f * wcrz[qq];
        float s2, c2; __sincosf(0.5f * wcrz[16 + qq], &s2, &c2);
        Wh2[qq] = make_float2(c2, s2);
        float se_, ce_; __sincosf(0.5f * wry[16 + qq], &se_, &ce_);
        We[qq] = make_float2(ce_, se_);
        __sincosf(0.5f * wry[qq], &wy, &wx);   // cis(wry0/2) for the low lanes
    } else {
        float xv = x[bb * 128 + (qq >> 2) * 32 + p * 4 + (qq & 3)] * scal[0];
        float ex = __expf(2.f * xv);
        float e = __fdividef(ex - 1.f, ex + 1.f) * PI_F;   // pi * tanh(xv)
        __sincosf(0.5f * e, &sh, &ch);                     // the ONLY chained sincos
    }
    float cwm = __shfl_sync(FULL, wx, 16 + qq);
    float swm = __shfl_sync(FULL, wy, 16 + qq);
    if (lane < 16) {
        Wu[qq] = make_float2((ch - sh) * RS2, (ch + sh) * RS2);
        // cis((wry0+e)/2) = cis(wry0/2) * cis(e/2)
        Wm[qq] = make_float2(cwm * ch - swm * sh, swm * ch + cwm * sh);
    }
    __syncwarp();

    // window qubits: local bit k <-> global qubit q-3+k (mod 16)
    int p0 = (q + 13) & 15, p1 = (q + 14) & 15, p2 = (q + 15) & 15;
    int p4 = (q + 1) & 15,  p5 = (q + 2) & 15,  p6 = (q + 3) & 15;
    int b0 = lane & 1, b1 = (lane >> 1) & 1, b2 = (lane >> 2) & 1;
    int b4 = (lane >> 3) & 1, b6 = (lane >> 4) & 1;

    // warp-broadcast smem reads
    float2 U0 = Wu[p0], U1 = Wu[p1], U2 = Wu[p2];
    float2 Uq = Wu[q],  U4 = Wu[p4], U5 = Wu[p5], U6 = Wu[p6];
    float h1p0 = Wh1[p0], h1p1 = Wh1[p1], h1p2 = Wh1[p2];
    float h1q = Wh1[q], h1p4 = Wh1[p4], h1p5 = Wh1[p5];
    float2 M1 = Wm[p1], Mq = Wm[q], M5 = Wm[p5];
    float2 Ha = Wh2[p1], Hb = Wh2[q];
    float2 E = We[q];

    // init product amplitude over lane bits
    float base = (b0 ? U0.y : U0.x) * (b1 ? U1.y : U1.x) * (b2 ? U2.y : U2.x)
               * (b4 ? U4.y : U4.x) * (b6 ? U6.y : U6.x);
    // D1 ring phase: control? (target? +h : -h) : 0 over the 6 window pairs
    float phiL = (b0 ? (b1 ? h1p0 : -h1p0) : 0.f)
               + (b1 ? (b2 ? h1p1 : -h1p1) : 0.f);
    float A0 = b2 ? -h1p2 : 0.f;                               // b3 = 0
    float A1 = (b2 ? h1p2 : 0.f) + (b4 ? h1q : -h1q);          // b3 = 1
    float B0 = b4 ? -h1p4 : 0.f;                               // b5 = 0
    float B1 = (b4 ? h1p4 : 0.f) + (b6 ? h1p5 : -h1p5);        // b5 = 1

    float vr[4], vi[4];
    {
        float ang[4] = { phiL + A0 + B0, phiL + A1 + B0,
                         phiL + A0 + B1, phiL + A1 + B1 };     // j = b3 + 2*b5
        float fj[4] = { base * Uq.x * U5.x, base * Uq.y * U5.x,
                        base * Uq.x * U5.y, base * Uq.y * U5.y };
#pragma unroll
        for (int j = 0; j < 4; j++) {
            float s_, c_; __sincosf(ang[j], &s_, &c_);
            vr[j] = fj[j] * c_; vi[j] = fj[j] * s_;
        }
    }
    // mid RY on qubit q-2 (lane bit 1): the only shfl gate
    {
        float cc = M1.x, sg = b1 ? M1.y : -M1.y;
#pragma unroll
        for (int j = 0; j < 4; j++) {
            float pr = __shfl_xor_sync(FULL, vr[j], 2);
            float pi = __shfl_xor_sync(FULL, vi[j], 2);
            vr[j] = cc * vr[j] + sg * pr;
            vi[j] = cc * vi[j] + sg * pi;
        }
    }
    // mid RY on qubit q (register bit b3): pairs (0,1),(2,3)
    {
        float cc = Mq.x, ss = Mq.y;
#pragma unroll
        for (int jj = 0; jj < 4; jj += 2) {
            float r0 = vr[jj], r1 = vr[jj + 1];
            vr[jj] = cc * r0 - ss * r1;  vr[jj + 1] = ss * r0 + cc * r1;
            float i0 = vi[jj], i1 = vi[jj + 1];
            vi[jj] = cc * i0 - ss * i1;  vi[jj + 1] = ss * i0 + cc * i1;
        }
    }
    // mid RY on qubit q+2 (register bit b5): pairs (0,2),(1,3)
    {
        float cc = M5.x, ss = M5.y;
#pragma unroll
        for (int jj = 0; jj < 2; jj++) {
            float r0 = vr[jj], r1 = vr[jj + 2];
            vr[jj] = cc * r0 - ss * r1;  vr[jj + 2] = ss * r0 + cc * r1;
            float i0 = vi[jj], i1 = vi[jj + 2];
            vi[jj] = cc * i0 - ss * i1;  vi[jj + 2] = ss * i0 + cc * i1;
        }
    }
    // D2 diagonal: CRZ(q-2 -> q) uses (b1,b3); CRZ(q -> q+2) uses (b3,b5)
    {
        float pr0 = b1 ? Ha.x : 1.f, pi0 = b1 ? -Ha.y : 0.f;   // b3 = 0 factor
        float prA = pr0,            piA = b1 ?  Ha.y : 0.f;    // b3 = 1 base
#pragma unroll
        for (int jj = 0; jj < 4; jj += 2) {                    // j = 0, 2 (b3 = 0)
            float nr = vr[jj] * pr0 - vi[jj] * pi0;
            vi[jj] = vr[jj] * pi0 + vi[jj] * pr0;
            vr[jj] = nr;
        }
        float pr1 = prA * Hb.x + piA * Hb.y, pi1 = -prA * Hb.y + piA * Hb.x;
        float pr3 = prA * Hb.x - piA * Hb.y, pi3 =  prA * Hb.y + piA * Hb.x;
        float nr1 = vr[1] * pr1 - vi[1] * pi1;
        vi[1] = vr[1] * pi1 + vi[1] * pr1; vr[1] = nr1;
        float nr3 = vr[3] * pr3 - vi[3] * pi3;
        vi[3] = vr[3] * pi3 + vi[3] * pr3; vr[3] = nr3;
    }
    // end RY on qubit q (register bit b3)
    {
        float cc = E.x, ss = E.y;
#pragma unroll
        for (int jj = 0; jj < 4; jj += 2) {
            float r0 = vr[jj], r1 = vr[jj + 1];
            vr[jj] = cc * r0 - ss * r1;  vr[jj + 1] = ss * r0 + cc * r1;
            float i0 = vi[jj], i1 = vi[jj + 1];
            vi[jj] = cc * i0 - ss * i1;  vi[jj + 1] = ss * i0 + cc * i1;
        }
    }
    // z_q = sum (1 - 2*b3) |amp|^2 ; b3 = j&1
    float acc = (vr[0] * vr[0] + vi[0] * vi[0]) - (vr[1] * vr[1] + vi[1] * vi[1])
              + (vr[2] * vr[2] + vi[2] * vi[2]) - (vr[3] * vr[3] + vi[3] * vi[3]);
#pragma unroll
    for (int o = 16; o > 0; o >>= 1) acc += __shfl_down_sync(FULL, acc, o);
    if (lane == 0)
        out[bb * 128 + (q >> 2) * 32 + p * 4 + (q & 3)] = fminf(1.f, fmaxf(-1.f, acc));
}

extern "C" void kernel_launch(void* const* d_in, const int* in_sizes, int n_in,
                              void* d_out, int out_size) {
    const float* x    = (const float*)d_in[0];
    const float* wcrz = (const float*)d_in[1];
    const float* wry  = (const float*)d_in[2];
    const float* sc   = (const float*)d_in[3];
    (void)in_sizes; (void)n_in; (void)out_size;
    qmain<<<1024, 32>>>(x, wcrz, wry, sc, (float*)d_out);
}